// round 4
// baseline (speedup 1.0000x reference)
#include <cuda_runtime.h>
#include <cuda_bf16.h>
#include <cstdint>

// ---------------------------------------------------------------------------
// Problem constants
// ---------------------------------------------------------------------------
constexpr int DIM  = 1024;
constexpr int ROWS = 4096;   // BATCH * SEQ

// ---------------------------------------------------------------------------
// Device scratch (allocation-free per harness rules)
// fp32 operands split into bf16 (hi, lo):  v ~= hi + lo, |err| ~ 2^-17 |v|
// ---------------------------------------------------------------------------
__device__ __align__(16) __nv_bfloat16 g_xh[ROWS * DIM];
__device__ __align__(16) __nv_bfloat16 g_xl[ROWS * DIM];
__device__ __align__(16) __nv_bfloat16 g_wvh[DIM * DIM];
__device__ __align__(16) __nv_bfloat16 g_wvl[DIM * DIM];
__device__ __align__(16) __nv_bfloat16 g_wph[DIM * DIM];
__device__ __align__(16) __nv_bfloat16 g_wpl[DIM * DIM];
__device__ __align__(16) __nv_bfloat16 g_mh[DIM * DIM];   // M = Wv @ Wp (hi)
__device__ __align__(16) __nv_bfloat16 g_ml[DIM * DIM];   // M (lo)
__device__ float g_c[DIM];                                 // fused bias
constexpr int KSLICES = 16;
__device__ float g_cpart[KSLICES * DIM];                   // bias partials

// ---------------------------------------------------------------------------
// Helpers
// ---------------------------------------------------------------------------
__device__ __forceinline__ uint32_t smem_u32(const void* p) {
    uint32_t a;
    asm("{ .reg .u64 t; cvta.to.shared.u64 t, %1; cvt.u32.u64 %0, t; }" : "=r"(a) : "l"(p));
    return a;
}
__device__ __forceinline__ void cp16(uint32_t dst, const void* src) {
    asm volatile("cp.async.cg.shared.global [%0], [%1], 16;" :: "r"(dst), "l"(src));
}
#define CP_COMMIT() asm volatile("cp.async.commit_group;" ::: "memory")

__device__ __forceinline__ void mma_bf16(float d[4], const uint32_t a[4], const uint32_t b[2]) {
    asm volatile(
        "mma.sync.aligned.m16n8k16.row.col.f32.bf16.bf16.f32 "
        "{%0,%1,%2,%3}, {%4,%5,%6,%7}, {%8,%9}, {%0,%1,%2,%3};"
        : "+f"(d[0]), "+f"(d[1]), "+f"(d[2]), "+f"(d[3])
        : "r"(a[0]), "r"(a[1]), "r"(a[2]), "r"(a[3]), "r"(b[0]), "r"(b[1]));
}

// ---------------------------------------------------------------------------
// Split kernel: fp32 [rows x cols] (leading dim ld) -> bf16 hi/lo (dense)
// ---------------------------------------------------------------------------
__global__ void split_kernel(const float* __restrict__ in, int ld,
                             __nv_bfloat16* __restrict__ hi,
                             __nv_bfloat16* __restrict__ lo,
                             int rows, int cols)
{
    const int idx = blockIdx.x * blockDim.x + threadIdx.x;   // one float4
    const int c4 = cols >> 2;
    if (idx >= rows * c4) return;
    const int r = idx / c4;
    const int c = (idx - r * c4) << 2;
    float4 v = *reinterpret_cast<const float4*>(in + (size_t)r * ld + c);
    __nv_bfloat16 hx = __float2bfloat16(v.x), hy = __float2bfloat16(v.y);
    __nv_bfloat16 hz = __float2bfloat16(v.z), hw = __float2bfloat16(v.w);
    __nv_bfloat16 lx = __float2bfloat16(v.x - __bfloat162float(hx));
    __nv_bfloat16 ly = __float2bfloat16(v.y - __bfloat162float(hy));
    __nv_bfloat16 lz = __float2bfloat16(v.z - __bfloat162float(hz));
    __nv_bfloat16 lw = __float2bfloat16(v.w - __bfloat162float(hw));
    __nv_bfloat162* ph = reinterpret_cast<__nv_bfloat162*>(hi + (size_t)r * cols + c);
    ph[0] = __nv_bfloat162(hx, hy);  ph[1] = __nv_bfloat162(hz, hw);
    __nv_bfloat162* pl = reinterpret_cast<__nv_bfloat162*>(lo + (size_t)r * cols + c);
    pl[0] = __nv_bfloat162(lx, ly);  pl[1] = __nv_bfloat162(lz, lw);
}

// ---------------------------------------------------------------------------
// HMMA GEMM with fp32 emulation via bf16 split-3 over K' = 3K sections:
//   sec0: Ah*Bh, sec1: Ah*Bl, sec2: Al*Bh   (AlBl dropped, ~2^-16)
// CTA tile 128x128, 8 warps of 64x32, KC=64 chunks, cp.async 4-stage pipe.
// Output: either fp32 C (+ bias) or split bf16 (Chi, Clo).
// ---------------------------------------------------------------------------
constexpr int BM = 128, BN = 128, KC = 64;
constexpr int NSTAGE = 4;
constexpr int APITCH = 144;                 // 128B data + 16B pad (bank-safe)
constexpr int BPITCH = 272;                 // 256B data + 16B pad
constexpr int A_BYTES = BM * APITCH;        // 18432
constexpr int B_BYTES = KC * BPITCH;        // 17408
constexpr int STAGE_BYTES = A_BYTES + B_BYTES;
constexpr int SMEMT = NSTAGE * STAGE_BYTES; // 143360

__device__ __forceinline__ void issue_chunk(
    uint32_t sbase, int st,
    const __nv_bfloat16* Aptr, const __nv_bfloat16* Bptr,
    int lda, int ldb, int m0, int n0, int k0, int tid)
{
    const uint32_t sA = sbase + st * STAGE_BYTES;
    const uint32_t sB = sA + A_BYTES;
    const int arow = tid >> 3, ack = tid & 7;
    const int brow = tid >> 4, bck = tid & 15;
    #pragma unroll
    for (int p = 0; p < 4; p++) {
        const int r = arow + p * 32;
        cp16(sA + r * APITCH + ack * 16,
             Aptr + (size_t)(m0 + r) * lda + k0 + ack * 8);
        const int kr = brow + p * 16;
        cp16(sB + kr * BPITCH + bck * 16,
             Bptr + (size_t)(k0 + kr) * ldb + n0 + bck * 8);
    }
    CP_COMMIT();
}

__global__ __launch_bounds__(256, 1)
void gemm_bf16x3(const __nv_bfloat16* __restrict__ Ah, const __nv_bfloat16* __restrict__ Al, int lda,
                 const __nv_bfloat16* __restrict__ Bh, const __nv_bfloat16* __restrict__ Bl, int ldb,
                 float* __restrict__ Cf, const float* __restrict__ bias,
                 __nv_bfloat16* __restrict__ Chi, __nv_bfloat16* __restrict__ Clo,
                 int ldc, int K)
{
    extern __shared__ char smem[];
    const uint32_t sbase = smem_u32(smem);
    const int tid  = threadIdx.x;
    const int wid  = tid >> 5;
    const int lane = tid & 31;
    const int wr   = wid >> 2;     // 0..1  (warp row: 64 rows each)
    const int wc   = wid & 3;      // 0..3  (warp col: 32 cols each)
    const int m0   = blockIdx.y * BM;
    const int n0   = blockIdx.x * BN;

    const int NSEC = K / KC;       // chunks per section
    const int NCH  = 3 * NSEC;

    // section -> operand pointers + k0
    auto chunk_src = [&](int ch, const __nv_bfloat16*& Ap, const __nv_bfloat16*& Bp, int& k0) {
        const int sec = ch / NSEC;
        const int kk  = ch - sec * NSEC;
        Ap = (sec < 2) ? Ah : Al;
        Bp = (sec == 1) ? Bl : Bh;
        k0 = kk * KC;
    };

    float d[4][4][4];
    #pragma unroll
    for (int mi = 0; mi < 4; mi++)
        #pragma unroll
        for (int ni = 0; ni < 4; ni++)
            #pragma unroll
            for (int r = 0; r < 4; r++) d[mi][ni][r] = 0.0f;

    // Prologue: fill NSTAGE-1 stages
    #pragma unroll
    for (int s = 0; s < NSTAGE - 1; s++) {
        const __nv_bfloat16 *Ap, *Bp; int k0;
        chunk_src(s, Ap, Bp, k0);
        issue_chunk(sbase, s, Ap, Bp, lda, ldb, m0, n0, k0, tid);
    }

    for (int ch = 0; ch < NCH; ch++) {
        if (ch + NSTAGE - 1 < NCH) {
            const __nv_bfloat16 *Ap, *Bp; int k0;
            chunk_src(ch + NSTAGE - 1, Ap, Bp, k0);
            issue_chunk(sbase, (ch + NSTAGE - 1) % NSTAGE, Ap, Bp, lda, ldb, m0, n0, k0, tid);
            asm volatile("cp.async.wait_group %0;" :: "n"(NSTAGE - 1) : "memory");
        } else {
            const int remaining = NCH - 1 - ch;   // groups still in flight after this one
            if (remaining == 2)      asm volatile("cp.async.wait_group 2;" ::: "memory");
            else if (remaining == 1) asm volatile("cp.async.wait_group 1;" ::: "memory");
            else                     asm volatile("cp.async.wait_group 0;" ::: "memory");
        }
        __syncthreads();

        const uint32_t sA = sbase + (ch % NSTAGE) * STAGE_BYTES;
        const uint32_t sB = sA + A_BYTES;

        #pragma unroll
        for (int ki = 0; ki < KC / 16; ki++) {
            uint32_t a[4][4];
            #pragma unroll
            for (int mi = 0; mi < 4; mi++) {
                const uint32_t addr = sA
                    + (uint32_t)(wr * 64 + mi * 16 + (lane & 15)) * APITCH
                    + (uint32_t)((lane >> 4) * 8 + ki * 16) * 2;
                asm volatile("ldmatrix.sync.aligned.m8n8.x4.shared.b16 {%0,%1,%2,%3}, [%4];"
                    : "=r"(a[mi][0]), "=r"(a[mi][1]), "=r"(a[mi][2]), "=r"(a[mi][3])
                    : "r"(addr));
            }
            uint32_t b[4][2];
            #pragma unroll
            for (int t = 0; t < 2; t++) {
                const uint32_t addr = sB
                    + (uint32_t)(ki * 16 + (lane & 15)) * BPITCH
                    + (uint32_t)(wc * 32 + t * 16 + (lane >> 4) * 8) * 2;
                uint32_t r0, r1, r2, r3;
                asm volatile("ldmatrix.sync.aligned.m8n8.x4.trans.shared.b16 {%0,%1,%2,%3}, [%4];"
                    : "=r"(r0), "=r"(r1), "=r"(r2), "=r"(r3) : "r"(addr));
                b[2 * t][0] = r0;  b[2 * t][1] = r1;
                b[2 * t + 1][0] = r2;  b[2 * t + 1][1] = r3;
            }
            #pragma unroll
            for (int mi = 0; mi < 4; mi++)
                #pragma unroll
                for (int ni = 0; ni < 4; ni++)
                    mma_bf16(d[mi][ni], a[mi], b[ni]);
        }
        __syncthreads();
    }

    // ---- Epilogue ----
    #pragma unroll
    for (int mi = 0; mi < 4; mi++) {
        const int mrow = m0 + wr * 64 + mi * 16 + (lane >> 2);
        #pragma unroll
        for (int ni = 0; ni < 4; ni++) {
            const int ncol = n0 + wc * 32 + ni * 8 + (lane & 3) * 2;
            #pragma unroll
            for (int half = 0; half < 2; half++) {     // rows mrow, mrow+8
                const int r = mrow + half * 8;
                float v0 = d[mi][ni][half * 2 + 0];
                float v1 = d[mi][ni][half * 2 + 1];
                if (Cf != nullptr) {
                    if (bias != nullptr) { v0 += bias[ncol]; v1 += bias[ncol + 1]; }
                    float2 o; o.x = v0; o.y = v1;
                    *reinterpret_cast<float2*>(Cf + (size_t)r * ldc + ncol) = o;
                } else {
                    __nv_bfloat16 h0 = __float2bfloat16(v0);
                    __nv_bfloat16 h1 = __float2bfloat16(v1);
                    __nv_bfloat16 l0 = __float2bfloat16(v0 - __bfloat162float(h0));
                    __nv_bfloat16 l1 = __float2bfloat16(v1 - __bfloat162float(h1));
                    *reinterpret_cast<__nv_bfloat162*>(Chi + (size_t)r * ldc + ncol) = __nv_bfloat162(h0, h1);
                    *reinterpret_cast<__nv_bfloat162*>(Clo + (size_t)r * ldc + ncol) = __nv_bfloat162(l0, l1);
                }
            }
        }
    }
}

// ---------------------------------------------------------------------------
// Fused bias, parallel: c[j] = sum_k b_v[k] * w_proj[k, j] + b_proj[j]
// Phase A: partial sums over K slices (coalesced along j). Phase B: reduce.
// ---------------------------------------------------------------------------
__global__ void bias_partial_kernel(const float* __restrict__ b_qkv,
                                    const float* __restrict__ w_proj)
{
    const int j  = blockIdx.x * blockDim.x + threadIdx.x;   // 0..DIM-1
    const int s  = blockIdx.y;                              // k-slice
    const int kb = s * (DIM / KSLICES);
    float acc = 0.0f;
    #pragma unroll 8
    for (int k = 0; k < DIM / KSLICES; k++)
        acc += b_qkv[2 * DIM + kb + k] * w_proj[(size_t)(kb + k) * DIM + j];
    g_cpart[s * DIM + j] = acc;
}

__global__ void bias_reduce_kernel(const float* __restrict__ b_proj)
{
    const int j = blockIdx.x * blockDim.x + threadIdx.x;
    if (j >= DIM) return;
    float acc = b_proj[j];
    #pragma unroll
    for (int s = 0; s < KSLICES; s++) acc += g_cpart[s * DIM + j];
    g_c[j] = acc;
}

// ---------------------------------------------------------------------------
// kernel_launch
// Math: softmax rows sum to 1 and the reference's final einsum contracts k
// over attn only, so out == v. Head permutations cancel on flattened layout:
//   out = x @ (w_qkv[:,2C:3C] @ w_proj) + (b_qkv[2C:3C] @ w_proj + b_proj)
// ---------------------------------------------------------------------------
extern "C" void kernel_launch(void* const* d_in, const int* in_sizes, int n_in,
                              void* d_out, int out_size)
{
    const float* x      = (const float*)d_in[0];  // [4096, 1024]
    const float* w_qkv  = (const float*)d_in[1];  // [1024, 3072]
    const float* b_qkv  = (const float*)d_in[2];  // [3072]
    const float* w_proj = (const float*)d_in[3];  // [1024, 1024]
    const float* b_proj = (const float*)d_in[4];  // [1024]
    float* out = (float*)d_out;                   // [4096, 1024]

    __nv_bfloat16 *xh, *xl, *wvh, *wvl, *wph, *wpl, *mh, *ml;
    float* pc;
    cudaGetSymbolAddress((void**)&xh,  g_xh);
    cudaGetSymbolAddress((void**)&xl,  g_xl);
    cudaGetSymbolAddress((void**)&wvh, g_wvh);
    cudaGetSymbolAddress((void**)&wvl, g_wvl);
    cudaGetSymbolAddress((void**)&wph, g_wph);
    cudaGetSymbolAddress((void**)&wpl, g_wpl);
    cudaGetSymbolAddress((void**)&mh,  g_mh);
    cudaGetSymbolAddress((void**)&ml,  g_ml);
    cudaGetSymbolAddress((void**)&pc,  g_c);

    cudaFuncSetAttribute(gemm_bf16x3, cudaFuncAttributeMaxDynamicSharedMemorySize, SMEMT);

    // 1) Split conversions
    split_kernel<<<(DIM * DIM / 4 + 255) / 256, 256>>>(w_qkv + 2 * DIM, 3 * DIM, wvh, wvl, DIM, DIM);
    split_kernel<<<(DIM * DIM / 4 + 255) / 256, 256>>>(w_proj, DIM, wph, wpl, DIM, DIM);
    split_kernel<<<(ROWS * DIM / 4 + 255) / 256, 256>>>(x, DIM, xh, xl, ROWS, DIM);

    // 2) fused bias (parallel two-phase, no atomics)
    {
        dim3 grid(DIM / 256, KSLICES);
        bias_partial_kernel<<<grid, 256>>>(b_qkv, w_proj);
        bias_reduce_kernel<<<DIM / 256, 256>>>(b_proj);
    }

    // 3) M = Wv @ Wp  -> split bf16 output
    {
        dim3 grid(DIM / BN, DIM / BM);   // 8 x 8
        gemm_bf16x3<<<grid, 256, SMEMT>>>(wvh, wvl, DIM, wph, wpl, DIM,
                                          nullptr, nullptr, mh, ml, DIM, DIM);
    }
    // 4) out = x @ M + c  (fp32 output)
    {
        dim3 grid(DIM / BN, ROWS / BM);  // 8 x 32
        gemm_bf16x3<<<grid, 256, SMEMT>>>(xh, xl, DIM, mh, ml, DIM,
                                          out, pc, nullptr, nullptr, DIM, DIM);
    }
}

// round 5
// speedup vs baseline: 1.3269x; 1.3269x over previous
#include <cuda_runtime.h>
#include <cuda_bf16.h>
#include <cstdint>

// ---------------------------------------------------------------------------
// Problem constants
// ---------------------------------------------------------------------------
constexpr int DIM  = 1024;
constexpr int ROWS = 4096;   // BATCH * SEQ

// ---------------------------------------------------------------------------
// Device scratch (allocation-free per harness rules)
// fp32 operands split into bf16 (hi, lo):  v ~= hi + lo, |err| ~ 2^-17 |v|
// ---------------------------------------------------------------------------
__device__ __align__(16) __nv_bfloat16 g_xh[ROWS * DIM];
__device__ __align__(16) __nv_bfloat16 g_xl[ROWS * DIM];
__device__ __align__(16) __nv_bfloat16 g_wvh[DIM * DIM];
__device__ __align__(16) __nv_bfloat16 g_wvl[DIM * DIM];
__device__ __align__(16) __nv_bfloat16 g_wph[DIM * DIM];
__device__ __align__(16) __nv_bfloat16 g_wpl[DIM * DIM];
__device__ __align__(16) __nv_bfloat16 g_mh[DIM * DIM];   // M = Wv @ Wp (hi)
__device__ __align__(16) __nv_bfloat16 g_ml[DIM * DIM];   // M (lo)
__device__ __align__(16) float g_p0[DIM * DIM];           // split-K partial 0
__device__ __align__(16) float g_p1[DIM * DIM];           // split-K partial 1
__device__ float g_c[DIM];                                 // fused bias
constexpr int KSLICES = 16;
__device__ float g_cpart[KSLICES * DIM];                   // bias partials

// ---------------------------------------------------------------------------
// Helpers
// ---------------------------------------------------------------------------
__device__ __forceinline__ uint32_t smem_u32(const void* p) {
    uint32_t a;
    asm("{ .reg .u64 t; cvta.to.shared.u64 t, %1; cvt.u32.u64 %0, t; }" : "=r"(a) : "l"(p));
    return a;
}
__device__ __forceinline__ void cp16(uint32_t dst, const void* src) {
    asm volatile("cp.async.cg.shared.global [%0], [%1], 16;" :: "r"(dst), "l"(src));
}
#define CP_COMMIT() asm volatile("cp.async.commit_group;" ::: "memory")

__device__ __forceinline__ void mma_bf16(float d[4], const uint32_t a[4], const uint32_t b[2]) {
    asm volatile(
        "mma.sync.aligned.m16n8k16.row.col.f32.bf16.bf16.f32 "
        "{%0,%1,%2,%3}, {%4,%5,%6,%7}, {%8,%9}, {%0,%1,%2,%3};"
        : "+f"(d[0]), "+f"(d[1]), "+f"(d[2]), "+f"(d[3])
        : "r"(a[0]), "r"(a[1]), "r"(a[2]), "r"(a[3]), "r"(b[0]), "r"(b[1]));
}

// ---------------------------------------------------------------------------
// Split kernel: fp32 [rows x cols] (leading dim ld) -> bf16 hi/lo (dense)
// ---------------------------------------------------------------------------
__global__ void split_kernel(const float* __restrict__ in, int ld,
                             __nv_bfloat16* __restrict__ hi,
                             __nv_bfloat16* __restrict__ lo,
                             int rows, int cols)
{
    const int idx = blockIdx.x * blockDim.x + threadIdx.x;   // one float4
    const int c4 = cols >> 2;
    if (idx >= rows * c4) return;
    const int r = idx / c4;
    const int c = (idx - r * c4) << 2;
    float4 v = *reinterpret_cast<const float4*>(in + (size_t)r * ld + c);
    __nv_bfloat16 hx = __float2bfloat16(v.x), hy = __float2bfloat16(v.y);
    __nv_bfloat16 hz = __float2bfloat16(v.z), hw = __float2bfloat16(v.w);
    __nv_bfloat16 lx = __float2bfloat16(v.x - __bfloat162float(hx));
    __nv_bfloat16 ly = __float2bfloat16(v.y - __bfloat162float(hy));
    __nv_bfloat16 lz = __float2bfloat16(v.z - __bfloat162float(hz));
    __nv_bfloat16 lw = __float2bfloat16(v.w - __bfloat162float(hw));
    __nv_bfloat162* ph = reinterpret_cast<__nv_bfloat162*>(hi + (size_t)r * cols + c);
    ph[0] = __nv_bfloat162(hx, hy);  ph[1] = __nv_bfloat162(hz, hw);
    __nv_bfloat162* pl = reinterpret_cast<__nv_bfloat162*>(lo + (size_t)r * cols + c);
    pl[0] = __nv_bfloat162(lx, ly);  pl[1] = __nv_bfloat162(lz, lw);
}

// ---------------------------------------------------------------------------
// Combine split-K partials and split result to bf16 hi/lo:  M = p0 + p1
// ---------------------------------------------------------------------------
__global__ void combine_split_kernel(__nv_bfloat16* __restrict__ hi,
                                     __nv_bfloat16* __restrict__ lo)
{
    const int idx = blockIdx.x * blockDim.x + threadIdx.x;   // one float4
    if (idx >= DIM * DIM / 4) return;
    const int c = idx << 2;
    float4 a = *reinterpret_cast<const float4*>(g_p0 + c);
    float4 b = *reinterpret_cast<const float4*>(g_p1 + c);
    float vx = a.x + b.x, vy = a.y + b.y, vz = a.z + b.z, vw = a.w + b.w;
    __nv_bfloat16 hx = __float2bfloat16(vx), hy = __float2bfloat16(vy);
    __nv_bfloat16 hz = __float2bfloat16(vz), hw = __float2bfloat16(vw);
    __nv_bfloat16 lx = __float2bfloat16(vx - __bfloat162float(hx));
    __nv_bfloat16 ly = __float2bfloat16(vy - __bfloat162float(hy));
    __nv_bfloat16 lz = __float2bfloat16(vz - __bfloat162float(hz));
    __nv_bfloat16 lw = __float2bfloat16(vw - __bfloat162float(hw));
    __nv_bfloat162* ph = reinterpret_cast<__nv_bfloat162*>(hi + c);
    ph[0] = __nv_bfloat162(hx, hy);  ph[1] = __nv_bfloat162(hz, hw);
    __nv_bfloat162* pl = reinterpret_cast<__nv_bfloat162*>(lo + c);
    pl[0] = __nv_bfloat162(lx, ly);  pl[1] = __nv_bfloat162(lz, lw);
}

// ---------------------------------------------------------------------------
// HMMA GEMM with fp32 emulation via bf16 split-3 over K' = 3K sections:
//   sec0: Ah*Bh, sec1: Ah*Bl, sec2: Al*Bh   (AlBl dropped, ~2^-16)
// CTA tile 128x128, 8 warps of 64x32, KC=64 chunks, cp.async 3-stage pipe.
// Split-K: blockIdx.z selects K window [z*K, (z+1)*K) and output buffer.
// ---------------------------------------------------------------------------
constexpr int BM = 128, BN = 128, KC = 64;
constexpr int NSTAGE = 3;
constexpr int APITCH = 144;                 // 128B data + 16B pad (bank-safe)
constexpr int BPITCH = 272;                 // 256B data + 16B pad
constexpr int A_BYTES = BM * APITCH;        // 18432
constexpr int B_BYTES = KC * BPITCH;        // 17408
constexpr int STAGE_BYTES = A_BYTES + B_BYTES;
constexpr int SMEMT = NSTAGE * STAGE_BYTES; // 107520 -> 2 CTAs/SM

__device__ __forceinline__ void issue_chunk(
    uint32_t sbase, int st,
    const __nv_bfloat16* Aptr, const __nv_bfloat16* Bptr,
    int lda, int ldb, int m0, int n0, int k0, int tid)
{
    const uint32_t sA = sbase + st * STAGE_BYTES;
    const uint32_t sB = sA + A_BYTES;
    const int arow = tid >> 3, ack = tid & 7;
    const int brow = tid >> 4, bck = tid & 15;
    #pragma unroll
    for (int p = 0; p < 4; p++) {
        const int r = arow + p * 32;
        cp16(sA + r * APITCH + ack * 16,
             Aptr + (size_t)(m0 + r) * lda + k0 + ack * 8);
        const int kr = brow + p * 16;
        cp16(sB + kr * BPITCH + bck * 16,
             Bptr + (size_t)(k0 + kr) * ldb + n0 + bck * 8);
    }
    CP_COMMIT();
}

__global__ __launch_bounds__(256, 2)
void gemm_bf16x3(const __nv_bfloat16* __restrict__ Ah, const __nv_bfloat16* __restrict__ Al, int lda,
                 const __nv_bfloat16* __restrict__ Bh, const __nv_bfloat16* __restrict__ Bl, int ldb,
                 float* __restrict__ Cf, float* __restrict__ Cf1,
                 const float* __restrict__ bias,
                 __nv_bfloat16* __restrict__ Chi, __nv_bfloat16* __restrict__ Clo,
                 int ldc, int K)
{
    extern __shared__ char smem[];
    const uint32_t sbase = smem_u32(smem);
    const int tid  = threadIdx.x;
    const int wid  = tid >> 5;
    const int lane = tid & 31;
    const int wr   = wid >> 2;     // 0..1  (warp row: 64 rows each)
    const int wc   = wid & 3;      // 0..3  (warp col: 32 cols each)
    const int m0   = blockIdx.y * BM;
    const int n0   = blockIdx.x * BN;
    const int z    = blockIdx.z;   // split-K index

    // Split-K window: shift operand pointers by z*K along the contraction dim
    Ah += (size_t)z * K;
    Al += (size_t)z * K;
    Bh += (size_t)z * K * ldb;
    Bl += (size_t)z * K * ldb;
    float* Csel = (z == 0) ? Cf : Cf1;

    const int NSEC = K / KC;       // chunks per section
    const int NCH  = 3 * NSEC;

    auto chunk_src = [&](int ch, const __nv_bfloat16*& Ap, const __nv_bfloat16*& Bp, int& k0) {
        const int sec = ch / NSEC;
        const int kk  = ch - sec * NSEC;
        Ap = (sec < 2) ? Ah : Al;
        Bp = (sec == 1) ? Bl : Bh;
        k0 = kk * KC;
    };

    float d[4][4][4];
    #pragma unroll
    for (int mi = 0; mi < 4; mi++)
        #pragma unroll
        for (int ni = 0; ni < 4; ni++)
            #pragma unroll
            for (int r = 0; r < 4; r++) d[mi][ni][r] = 0.0f;

    // Prologue: stages 0, 1
    #pragma unroll
    for (int s = 0; s < NSTAGE - 1; s++) {
        const __nv_bfloat16 *Ap, *Bp; int k0;
        chunk_src(s, Ap, Bp, k0);
        issue_chunk(sbase, s, Ap, Bp, lda, ldb, m0, n0, k0, tid);
    }

    for (int ch = 0; ch < NCH; ch++) {
        if (ch + 2 < NCH) {
            const __nv_bfloat16 *Ap, *Bp; int k0;
            chunk_src(ch + 2, Ap, Bp, k0);
            issue_chunk(sbase, (ch + 2) % NSTAGE, Ap, Bp, lda, ldb, m0, n0, k0, tid);
        }
        if (ch + 2 < NCH)       asm volatile("cp.async.wait_group 2;" ::: "memory");
        else if (ch + 1 < NCH)  asm volatile("cp.async.wait_group 1;" ::: "memory");
        else                    asm volatile("cp.async.wait_group 0;" ::: "memory");
        __syncthreads();

        const uint32_t sA = sbase + (ch % NSTAGE) * STAGE_BYTES;
        const uint32_t sB = sA + A_BYTES;

        #pragma unroll
        for (int ki = 0; ki < KC / 16; ki++) {
            uint32_t a[4][4];
            #pragma unroll
            for (int mi = 0; mi < 4; mi++) {
                const uint32_t addr = sA
                    + (uint32_t)(wr * 64 + mi * 16 + (lane & 15)) * APITCH
                    + (uint32_t)((lane >> 4) * 8 + ki * 16) * 2;
                asm volatile("ldmatrix.sync.aligned.m8n8.x4.shared.b16 {%0,%1,%2,%3}, [%4];"
                    : "=r"(a[mi][0]), "=r"(a[mi][1]), "=r"(a[mi][2]), "=r"(a[mi][3])
                    : "r"(addr));
            }
            uint32_t b[4][2];
            #pragma unroll
            for (int t = 0; t < 2; t++) {
                const uint32_t addr = sB
                    + (uint32_t)(ki * 16 + (lane & 15)) * BPITCH
                    + (uint32_t)(wc * 32 + t * 16 + (lane >> 4) * 8) * 2;
                uint32_t r0, r1, r2, r3;
                asm volatile("ldmatrix.sync.aligned.m8n8.x4.trans.shared.b16 {%0,%1,%2,%3}, [%4];"
                    : "=r"(r0), "=r"(r1), "=r"(r2), "=r"(r3) : "r"(addr));
                b[2 * t][0] = r0;  b[2 * t][1] = r1;
                b[2 * t + 1][0] = r2;  b[2 * t + 1][1] = r3;
            }
            #pragma unroll
            for (int mi = 0; mi < 4; mi++)
                #pragma unroll
                for (int ni = 0; ni < 4; ni++)
                    mma_bf16(d[mi][ni], a[mi], b[ni]);
        }
        __syncthreads();
    }

    // ---- Epilogue ----
    #pragma unroll
    for (int mi = 0; mi < 4; mi++) {
        const int mrow = m0 + wr * 64 + mi * 16 + (lane >> 2);
        #pragma unroll
        for (int ni = 0; ni < 4; ni++) {
            const int ncol = n0 + wc * 32 + ni * 8 + (lane & 3) * 2;
            #pragma unroll
            for (int half = 0; half < 2; half++) {     // rows mrow, mrow+8
                const int r = mrow + half * 8;
                float v0 = d[mi][ni][half * 2 + 0];
                float v1 = d[mi][ni][half * 2 + 1];
                if (Csel != nullptr) {
                    if (bias != nullptr) { v0 += bias[ncol]; v1 += bias[ncol + 1]; }
                    float2 o; o.x = v0; o.y = v1;
                    *reinterpret_cast<float2*>(Csel + (size_t)r * ldc + ncol) = o;
                } else {
                    __nv_bfloat16 h0 = __float2bfloat16(v0);
                    __nv_bfloat16 h1 = __float2bfloat16(v1);
                    __nv_bfloat16 l0 = __float2bfloat16(v0 - __bfloat162float(h0));
                    __nv_bfloat16 l1 = __float2bfloat16(v1 - __bfloat162float(h1));
                    *reinterpret_cast<__nv_bfloat162*>(Chi + (size_t)r * ldc + ncol) = __nv_bfloat162(h0, h1);
                    *reinterpret_cast<__nv_bfloat162*>(Clo + (size_t)r * ldc + ncol) = __nv_bfloat162(l0, l1);
                }
            }
        }
    }
}

// ---------------------------------------------------------------------------
// Fused bias, parallel: c[j] = sum_k b_v[k] * w_proj[k, j] + b_proj[j]
// ---------------------------------------------------------------------------
__global__ void bias_partial_kernel(const float* __restrict__ b_qkv,
                                    const float* __restrict__ w_proj)
{
    const int j  = blockIdx.x * blockDim.x + threadIdx.x;   // 0..DIM-1
    const int s  = blockIdx.y;                              // k-slice
    const int kb = s * (DIM / KSLICES);
    float acc = 0.0f;
    #pragma unroll 8
    for (int k = 0; k < DIM / KSLICES; k++)
        acc += b_qkv[2 * DIM + kb + k] * w_proj[(size_t)(kb + k) * DIM + j];
    g_cpart[s * DIM + j] = acc;
}

__global__ void bias_reduce_kernel(const float* __restrict__ b_proj)
{
    const int j = blockIdx.x * blockDim.x + threadIdx.x;
    if (j >= DIM) return;
    float acc = b_proj[j];
    #pragma unroll
    for (int s = 0; s < KSLICES; s++) acc += g_cpart[s * DIM + j];
    g_c[j] = acc;
}

// ---------------------------------------------------------------------------
// kernel_launch
// Math: softmax rows sum to 1 and the reference's final einsum contracts k
// over attn only, so out == v. Head permutations cancel on flattened layout:
//   out = x @ (w_qkv[:,2C:3C] @ w_proj) + (b_qkv[2C:3C] @ w_proj + b_proj)
// ---------------------------------------------------------------------------
extern "C" void kernel_launch(void* const* d_in, const int* in_sizes, int n_in,
                              void* d_out, int out_size)
{
    const float* x      = (const float*)d_in[0];  // [4096, 1024]
    const float* w_qkv  = (const float*)d_in[1];  // [1024, 3072]
    const float* b_qkv  = (const float*)d_in[2];  // [3072]
    const float* w_proj = (const float*)d_in[3];  // [1024, 1024]
    const float* b_proj = (const float*)d_in[4];  // [1024]
    float* out = (float*)d_out;                   // [4096, 1024]

    __nv_bfloat16 *xh, *xl, *wvh, *wvl, *wph, *wpl, *mh, *ml;
    float *pc, *p0, *p1;
    cudaGetSymbolAddress((void**)&xh,  g_xh);
    cudaGetSymbolAddress((void**)&xl,  g_xl);
    cudaGetSymbolAddress((void**)&wvh, g_wvh);
    cudaGetSymbolAddress((void**)&wvl, g_wvl);
    cudaGetSymbolAddress((void**)&wph, g_wph);
    cudaGetSymbolAddress((void**)&wpl, g_wpl);
    cudaGetSymbolAddress((void**)&mh,  g_mh);
    cudaGetSymbolAddress((void**)&ml,  g_ml);
    cudaGetSymbolAddress((void**)&pc,  g_c);
    cudaGetSymbolAddress((void**)&p0,  g_p0);
    cudaGetSymbolAddress((void**)&p1,  g_p1);

    cudaFuncSetAttribute(gemm_bf16x3, cudaFuncAttributeMaxDynamicSharedMemorySize, SMEMT);

    // 1) Split conversions
    split_kernel<<<(DIM * DIM / 4 + 255) / 256, 256>>>(w_qkv + 2 * DIM, 3 * DIM, wvh, wvl, DIM, DIM);
    split_kernel<<<(DIM * DIM / 4 + 255) / 256, 256>>>(w_proj, DIM, wph, wpl, DIM, DIM);
    split_kernel<<<(ROWS * DIM / 4 + 255) / 256, 256>>>(x, DIM, xh, xl, ROWS, DIM);

    // 2) fused bias (parallel two-phase, no atomics)
    {
        dim3 grid(DIM / 256, KSLICES);
        bias_partial_kernel<<<grid, 256>>>(b_qkv, w_proj);
        bias_reduce_kernel<<<DIM / 256, 256>>>(b_proj);
    }

    // 3) M = Wv @ Wp, split-K x2 (128 CTAs) -> fp32 partials
    {
        dim3 grid(DIM / BN, DIM / BM, 2);   // 8 x 8 x 2
        gemm_bf16x3<<<grid, 256, SMEMT>>>(wvh, wvl, DIM, wph, wpl, DIM,
                                          p0, p1, nullptr, nullptr, nullptr,
                                          DIM, DIM / 2);
    }
    // 3b) combine partials + split to bf16 hi/lo
    combine_split_kernel<<<(DIM * DIM / 4 + 255) / 256, 256>>>(mh, ml);

    // 4) out = x @ M + c  (fp32 output)
    {
        dim3 grid(DIM / BN, ROWS / BM, 1);  // 8 x 32
        gemm_bf16x3<<<grid, 256, SMEMT>>>(xh, xl, DIM, mh, ml, DIM,
                                          out, nullptr, pc, nullptr, nullptr,
                                          DIM, DIM);
    }
}